// round 14
// baseline (speedup 1.0000x reference)
#include <cuda_runtime.h>
#include <stdint.h>

#define NN 16384
#define DD 32
#define LCAP 256
#define SENT 0x7FFFFFFF

// Adjacency lists WITH duplicates (dedup happens in agg via warp sort).
// g_cnt zero at load; agg resets each launch. No bitmask, nothing else to clear.
__device__ int g_list[(size_t)NN * LCAP];
__device__ int g_cnt[NN];

// 2 edges per thread: 4 independent returning atomicAdds front-batched,
// then the dependent list stores. Both directions always appended.
__global__ void __launch_bounds__(256) build_kernel(const int* __restrict__ src,
                                                    const int* __restrict__ dst,
                                                    int E2) {
    int t = blockIdx.x * blockDim.x + threadIdx.x;
    if (t >= E2) return;
    int2 s2 = __ldg(reinterpret_cast<const int2*>(src) + t);
    int2 d2 = __ldg(reinterpret_cast<const int2*>(dst) + t);

    int p0 = atomicAdd(&g_cnt[s2.x], 1);
    int p1 = atomicAdd(&g_cnt[d2.x], 1);
    int p2 = atomicAdd(&g_cnt[s2.y], 1);
    int p3 = atomicAdd(&g_cnt[d2.y], 1);
    if (p0 < LCAP) g_list[(size_t)s2.x * LCAP + p0] = d2.x;
    if (p1 < LCAP) g_list[(size_t)d2.x * LCAP + p1] = s2.x;
    if (p2 < LCAP) g_list[(size_t)s2.y * LCAP + p2] = d2.y;
    if (p3 < LCAP) g_list[(size_t)d2.y * LCAP + p3] = s2.y;
}

// Compare-exchange for one shfl step (both rows interleaved).
#define CE_SHFL(d, UPEXPR)                                              \
    do {                                                                \
        _Pragma("unroll")                                               \
        for (int k = 0; k < 4; k++) {                                   \
            int oa = __shfl_xor_sync(0xffffffffu, va[k], (d));          \
            int ob = __shfl_xor_sync(0xffffffffu, vb[k], (d));          \
            bool low = ((lane & (d)) == 0);                             \
            bool up  = (UPEXPR);                                        \
            if (low == up) { va[k] = min(va[k], oa); vb[k] = min(vb[k], ob); } \
            else           { va[k] = max(va[k], oa); vb[k] = max(vb[k], ob); } \
        }                                                               \
    } while (0)

#define CE_REG(i, j, asc)                                               \
    do {                                                                \
        int mna = min(va[i], va[j]), mxa = max(va[i], va[j]);           \
        va[i] = (asc) ? mna : mxa;  va[j] = (asc) ? mxa : mna;          \
        int mnb = min(vb[i], vb[j]), mxb = max(vb[i], vb[j]);           \
        vb[i] = (asc) ? mnb : mxb;  vb[j] = (asc) ? mxb : mnb;          \
    } while (0)

// TWO rows per warp. Sort-dedup (bitonic-128 per row), then R13 group-gather
// with keep-bit weights, dual fused epilogue. No global state to clear.
__global__ void __launch_bounds__(256, 4) agg_kernel(const float* __restrict__ x,
                                                     const float* __restrict__ W_agg,
                                                     const float* __restrict__ b_agg,
                                                     const float* __restrict__ W_upd,
                                                     const float* __restrict__ b_upd,
                                                     float* __restrict__ out) {
    __shared__ float WaggT[DD * DD];
    __shared__ float WupdT[DD * DD];
    __shared__ float bsum[DD];
    __shared__ float msgsm[16][DD];
    __shared__ float xsm[16][DD];
    __shared__ int   tailbuf[8][128];   // only used if cnt > 128 (never in practice)

    int tid  = threadIdx.x;
    int warp = tid >> 5;
    int lane = tid & 31;
    int r0   = blockIdx.x * 16 + warp * 2;
    int r1   = r0 + 1;

    const int* la = g_list + (size_t)r0 * LCAP;
    const int* lb = g_list + (size_t)r1 * LCAP;

    // Front-batched loads: 4 index words per row + cnts + own x rows.
    int va[4], vb[4];
#pragma unroll
    for (int k = 0; k < 4; k++) {
        va[k] = __ldg(la + (k << 5) + lane);
        vb[k] = __ldg(lb + (k << 5) + lane);
    }
    float xa = x[(size_t)r0 * DD + lane];
    float xb = x[(size_t)r1 * DD + lane];
    int ca = g_cnt[r0];  ca = ca < LCAP ? ca : LCAP;
    int cb = g_cnt[r1];  cb = cb < LCAP ? cb : LCAP;
    if (lane == 0) g_cnt[r0] = 0;
    if (lane == 1) g_cnt[r1] = 0;

    for (int i = tid; i < DD * DD; i += blockDim.x) {
        int c = i >> 5, d = i & 31;
        WaggT[d * DD + c] = W_agg[i];
        WupdT[d * DD + c] = W_upd[i];
    }
    if (tid < DD) bsum[tid] = b_agg[tid] + b_upd[tid];
    __syncthreads();

    // Sentinel-pad slots >= cnt (stale entries must not join the sort).
#pragma unroll
    for (int k = 0; k < 4; k++) {
        int pos = (k << 5) + lane;
        if (pos >= ca) va[k] = SENT;
        if (pos >= cb) vb[k] = SENT;
    }

    // ---- Bitonic sort of 128 elements, layout e = k*32 + lane, ascending.
    CE_SHFL(1, ((lane & 2) == 0));                       // p=2
    CE_SHFL(2, ((lane & 4) == 0));  CE_SHFL(1, ((lane & 4) == 0));   // p=4
    CE_SHFL(4, ((lane & 8) == 0));  CE_SHFL(2, ((lane & 8) == 0));  CE_SHFL(1, ((lane & 8) == 0)); // p=8
    CE_SHFL(8, ((lane & 16) == 0)); CE_SHFL(4, ((lane & 16) == 0));
    CE_SHFL(2, ((lane & 16) == 0)); CE_SHFL(1, ((lane & 16) == 0)); // p=16
    CE_SHFL(16, ((k & 1) == 0));  CE_SHFL(8, ((k & 1) == 0));  CE_SHFL(4, ((k & 1) == 0));
    CE_SHFL(2, ((k & 1) == 0));   CE_SHFL(1, ((k & 1) == 0));   // p=32
    CE_REG(0, 1, true);  CE_REG(2, 3, false);            // p=64, d=32
    CE_SHFL(16, ((k & 2) == 0));  CE_SHFL(8, ((k & 2) == 0));  CE_SHFL(4, ((k & 2) == 0));
    CE_SHFL(2, ((k & 2) == 0));   CE_SHFL(1, ((k & 2) == 0));   // p=64
    CE_REG(0, 2, true);  CE_REG(1, 3, true);             // p=128, d=64
    CE_REG(0, 1, true);  CE_REG(2, 3, true);             // p=128, d=32
    CE_SHFL(16, true);  CE_SHFL(8, true);  CE_SHFL(4, true);
    CE_SHFL(2, true);   CE_SHFL(1, true);                // p=128

    // ---- Mark keep = (v != predecessor) && (v != SENT); pack into bit 31.
    unsigned pka[4], pkb[4];
    {
        int t31a[3], t31b[3];
#pragma unroll
        for (int k = 0; k < 3; k++) {
            t31a[k] = __shfl_sync(0xffffffffu, va[k], 31);
            t31b[k] = __shfl_sync(0xffffffffu, vb[k], 31);
        }
#pragma unroll
        for (int k = 0; k < 4; k++) {
            int pra = __shfl_up_sync(0xffffffffu, va[k], 1);
            int prb = __shfl_up_sync(0xffffffffu, vb[k], 1);
            if (lane == 0) { pra = (k == 0) ? -1 : t31a[k - 1];
                             prb = (k == 0) ? -1 : t31b[k - 1]; }
            bool ka = (va[k] != pra) && (va[k] != SENT);
            bool kb = (vb[k] != prb) && (vb[k] != SENT);
            pka[k] = (unsigned)va[k] | (ka ? 0x80000000u : 0u);
            pkb[k] = (unsigned)vb[k] | (kb ? 0x80000000u : 0u);
        }
    }

    int g = lane >> 3;
    int q = lane & 7;
    const float4* x4 = reinterpret_cast<const float4*>(x);
    float4 Aa = make_float4(0.f, 0.f, 0.f, 0.f);
    float4 Ab = Aa;

    // ---- Slots 0..63 of BOTH rows: 32 independent LDG.128, straight-line.
#pragma unroll
    for (int w = 0; w < 2; w++) {
#pragma unroll
        for (int u = 0; u < 8; u++) {
            int slot = (u << 2) + g;
            unsigned pa = __shfl_sync(0xffffffffu, pka[w], slot);
            unsigned pb = __shfl_sync(0xffffffffu, pkb[w], slot);
            float wa = (float)(pa >> 31);
            float wb = (float)(pb >> 31);
            int ja = (int)(pa & 0x3FFFu);
            int jb = (int)(pb & 0x3FFFu);
            float4 vva = x4[(size_t)ja * 8 + q];
            float4 vvb = x4[(size_t)jb * 8 + q];
            Aa.x = fmaf(wa, vva.x, Aa.x); Aa.y = fmaf(wa, vva.y, Aa.y);
            Aa.z = fmaf(wa, vva.z, Aa.z); Aa.w = fmaf(wa, vva.w, Aa.w);
            Ab.x = fmaf(wb, vvb.x, Ab.x); Ab.y = fmaf(wb, vvb.y, Ab.y);
            Ab.z = fmaf(wb, vvb.z, Ab.z); Ab.w = fmaf(wb, vvb.w, Ab.w);
        }
    }
    // ---- Slots 64..95, 96..127 (guarded per row).
#pragma unroll
    for (int w = 2; w < 4; w++) {
        if (ca > (w << 5)) {
#pragma unroll
            for (int u = 0; u < 8; u++) {
                int slot = (u << 2) + g;
                unsigned pa = __shfl_sync(0xffffffffu, pka[w], slot);
                float wa = (float)(pa >> 31);
                int ja = (int)(pa & 0x3FFFu);
                float4 vva = x4[(size_t)ja * 8 + q];
                Aa.x = fmaf(wa, vva.x, Aa.x); Aa.y = fmaf(wa, vva.y, Aa.y);
                Aa.z = fmaf(wa, vva.z, Aa.z); Aa.w = fmaf(wa, vva.w, Aa.w);
            }
        }
        if (cb > (w << 5)) {
#pragma unroll
            for (int u = 0; u < 8; u++) {
                int slot = (u << 2) + g;
                unsigned pb = __shfl_sync(0xffffffffu, pkb[w], slot);
                float wb = (float)(pb >> 31);
                int jb = (int)(pb & 0x3FFFu);
                float4 vvb = x4[(size_t)jb * 8 + q];
                Ab.x = fmaf(wb, vvb.x, Ab.x); Ab.y = fmaf(wb, vvb.y, Ab.y);
                Ab.z = fmaf(wb, vvb.z, Ab.z); Ab.w = fmaf(wb, vvb.w, Ab.w);
            }
        }
    }

    // ---- Correctness fallback for cnt > 128 (Poisson(64): never fires).
    float ta = 0.f, tb = 0.f;
    if (ca > 128) {
        for (int kk = 128; kk < ca; kk++) {
            int jv = __ldg(la + kk);
            unsigned dup = __ballot_sync(0xffffffffu,
                va[0] == jv || va[1] == jv || va[2] == jv || va[3] == jv);
            for (int m = 0; m < kk - 128 && !dup; m++)
                dup = (tailbuf[warp][m] == jv) ? 1u : 0u;
            tailbuf[warp][kk - 128] = jv;
            if (!dup) ta += x[(size_t)jv * DD + lane];
        }
    }
    if (cb > 128) {
        for (int kk = 128; kk < cb; kk++) {
            int jv = __ldg(lb + kk);
            unsigned dup = __ballot_sync(0xffffffffu,
                vb[0] == jv || vb[1] == jv || vb[2] == jv || vb[3] == jv);
            for (int m = 0; m < kk - 128 && !dup; m++)
                dup = (tailbuf[warp][m] == jv) ? 1u : 0u;
            tailbuf[warp][kk - 128] = jv;
            if (!dup) tb += x[(size_t)jv * DD + lane];
        }
    }

    // Cross-group reduce for both rows (xor 8, xor 16).
#pragma unroll
    for (int off = 8; off <= 16; off <<= 1) {
        Aa.x += __shfl_xor_sync(0xffffffffu, Aa.x, off);
        Aa.y += __shfl_xor_sync(0xffffffffu, Aa.y, off);
        Aa.z += __shfl_xor_sync(0xffffffffu, Aa.z, off);
        Aa.w += __shfl_xor_sync(0xffffffffu, Aa.w, off);
        Ab.x += __shfl_xor_sync(0xffffffffu, Ab.x, off);
        Ab.y += __shfl_xor_sync(0xffffffffu, Ab.y, off);
        Ab.z += __shfl_xor_sync(0xffffffffu, Ab.z, off);
        Ab.w += __shfl_xor_sync(0xffffffffu, Ab.w, off);
    }
    int w2 = warp * 2;
    if (lane < 8) {
        *reinterpret_cast<float4*>(&msgsm[w2][q << 2])     = Aa;
        *reinterpret_cast<float4*>(&msgsm[w2 + 1][q << 2]) = Ab;
    }
    xsm[w2][lane]     = xa;
    xsm[w2 + 1][lane] = xb;
    __syncwarp();
    if (ca > 128) { msgsm[w2][lane] += ta; }
    if (cb > 128) { msgsm[w2 + 1][lane] += tb; }
    __syncwarp();

    // Dual fused epilogue.
    float oa = bsum[lane];
    float ob = oa;
#pragma unroll
    for (int d = 0; d < DD; d++) {
        float wag = WaggT[d * DD + lane];
        float wup = WupdT[d * DD + lane];
        oa = fmaf(msgsm[w2][d],     wag, fmaf(xsm[w2][d],     wup, oa));
        ob = fmaf(msgsm[w2 + 1][d], wag, fmaf(xsm[w2 + 1][d], wup, ob));
    }
    out[(size_t)r0 * DD + lane] = oa;
    out[(size_t)r1 * DD + lane] = ob;
}

extern "C" void kernel_launch(void* const* d_in, const int* in_sizes, int n_in,
                              void* d_out, int out_size) {
    const float* x     = (const float*)d_in[0];
    const int*   ei    = (const int*)d_in[1];
    const float* W_agg = (const float*)d_in[2];
    const float* b_agg = (const float*)d_in[3];
    const float* W_upd = (const float*)d_in[4];
    const float* b_upd = (const float*)d_in[5];
    float* out = (float*)d_out;

    int E  = in_sizes[1] / 2;
    int E2 = E / 2;

    build_kernel<<<(E2 + 255) / 256, 256>>>(ei, ei + E, E2);
    agg_kernel<<<NN / 16, 256>>>(x, W_agg, b_agg, W_upd, b_upd, out);
}

// round 15
// speedup vs baseline: 1.0529x; 1.0529x over previous
#include <cuda_runtime.h>
#include <stdint.h>

#define NN 16384
#define DD 32
#define WPR (NN / 32)     // 512 u32 per dedup-bitmask row
#define LCAP 256          // slots per node = 4 shards x 64 positions
#define SCAP 64           // positions per shard

// Canonical-pair dedup bitmask (32 MB; agg blanket-clears its stripes).
// Sharded lists: node row has 256 slots; shard s owns slots s, s+4, s+8, ...
// 4 sub-counters per node (g_cnt4) -> 4x less per-address atomic serialization.
__device__ uint32_t g_bits[(size_t)NN * WPR];
__device__ int g_list[(size_t)NN * LCAP];
__device__ int g_cnt4[NN * 4];

// 2 edges per thread. ONE canonical atomicOr per edge; on first-seen, append
// both directions into per-node SHARDED lists (stride-4 slots).
__global__ void __launch_bounds__(256) build_kernel(const int* __restrict__ src,
                                                    const int* __restrict__ dst,
                                                    int E2) {
    int t = blockIdx.x * blockDim.x + threadIdx.x;
    if (t >= E2) return;
    int2 s2 = __ldg(reinterpret_cast<const int2*>(src) + t);
    int2 d2 = __ldg(reinterpret_cast<const int2*>(dst) + t);

    int s[2] = {s2.x, s2.y};
    int d[2] = {d2.x, d2.y};

    int a[2], b[2];
#pragma unroll
    for (int i = 0; i < 2; i++) {
        a[i] = s[i] < d[i] ? s[i] : d[i];
        b[i] = s[i] < d[i] ? d[i] : s[i];
    }

    unsigned old[2];
#pragma unroll
    for (int i = 0; i < 2; i++)
        old[i] = atomicOr(&g_bits[(size_t)a[i] * WPR + (b[i] >> 5)], 1u << (b[i] & 31));

#pragma unroll
    for (int i = 0; i < 2; i++) {
        if (!(old[i] & (1u << (b[i] & 31)))) {    // first time pair {a,b} seen
            int sh = (t + i) & 3;
            int p = atomicAdd(&g_cnt4[a[i] * 4 + sh], 1);
            if (p < SCAP) g_list[(size_t)a[i] * LCAP + sh + (p << 2)] = b[i];
            if (a[i] != b[i]) {
                int sh2 = (t + i + 2) & 3;
                int p2 = atomicAdd(&g_cnt4[b[i] * 4 + sh2], 1);
                if (p2 < SCAP) g_list[(size_t)b[i] * LCAP + sh2 + (p2 << 2)] = a[i];
            }
        }
    }
}

// TWO rows per warp (R13 structure). Slot 32k+4u+g belongs to shard g at
// position 8k+u, so validity = (8k+u < c[g]) -- a scalar compare per lane.
__global__ void __launch_bounds__(256, 5) agg_kernel(const float* __restrict__ x,
                                                     const float* __restrict__ W_agg,
                                                     const float* __restrict__ b_agg,
                                                     const float* __restrict__ W_upd,
                                                     const float* __restrict__ b_upd,
                                                     float* __restrict__ out) {
    __shared__ float WaggT[DD * DD];   // [d][c] = W_agg[c][d]
    __shared__ float WupdT[DD * DD];
    __shared__ float bsum[DD];
    __shared__ float msgsm[16][DD];
    __shared__ float xsm[16][DD];

    int tid  = threadIdx.x;
    int warp = tid >> 5;
    int lane = tid & 31;
    int r0   = blockIdx.x * 16 + warp * 2;
    int r1   = r0 + 1;

    const int* la = g_list + (size_t)r0 * LCAP;
    const int* lb = g_list + (size_t)r1 * LCAP;

    // Front-batched independent loads: 4 index words per row + cnt4 + x rows.
    int ia[4], ib[4];
#pragma unroll
    for (int k = 0; k < 4; k++) {
        ia[k] = __ldg(la + (k << 5) + lane);
        ib[k] = __ldg(lb + (k << 5) + lane);
    }
    int4 ca4 = *reinterpret_cast<const int4*>(g_cnt4 + r0 * 4);
    int4 cb4 = *reinterpret_cast<const int4*>(g_cnt4 + r1 * 4);
    float xa = x[(size_t)r0 * DD + lane];
    float xb = x[(size_t)r1 * DD + lane];
    if (lane < 4)                 g_cnt4[r0 * 4 + lane]       = 0;
    else if (lane < 8)            g_cnt4[r1 * 4 + (lane - 4)] = 0;

    for (int i = tid; i < DD * DD; i += blockDim.x) {
        int c = i >> 5, d = i & 31;
        WaggT[d * DD + c] = W_agg[i];
        WupdT[d * DD + c] = W_upd[i];
    }
    if (tid < DD) bsum[tid] = b_agg[tid] + b_upd[tid];
    __syncthreads();

    int g = lane >> 3;        // gather group == shard id
    int q = lane & 7;         // float4 slot within a 128B row

    // Clamp shard counts to SCAP; per-lane count for its shard; warp maxima.
    int c0a = min(ca4.x, SCAP), c1a = min(ca4.y, SCAP),
        c2a = min(ca4.z, SCAP), c3a = min(ca4.w, SCAP);
    int c0b = min(cb4.x, SCAP), c1b = min(cb4.y, SCAP),
        c2b = min(cb4.z, SCAP), c3b = min(cb4.w, SCAP);
    int cga = (g == 0) ? c0a : (g == 1) ? c1a : (g == 2) ? c2a : c3a;
    int cgb = (g == 0) ? c0b : (g == 1) ? c1b : (g == 2) ? c2b : c3b;
    int mca = max(max(c0a, c1a), max(c2a, c3a));
    int mcb = max(max(c0b, c1b), max(c2b, c3b));

    const float4* x4 = reinterpret_cast<const float4*>(x);
    float4 Aa = make_float4(0.f, 0.f, 0.f, 0.f);
    float4 Ab = Aa;

    // ---- Words k=0,1 of BOTH rows: 32 independent LDG.128, straight-line.
#pragma unroll
    for (int k = 0; k < 2; k++) {
#pragma unroll
        for (int u = 0; u < 8; u++) {
            int slot = (u << 2) + g;
            int ja = __shfl_sync(0xffffffffu, ia[k], slot);
            int jb = __shfl_sync(0xffffffffu, ib[k], slot);
            float wa = ((k << 3) + u < cga) ? 1.0f : 0.0f;   // pos = 8k+u
            float wb = ((k << 3) + u < cgb) ? 1.0f : 0.0f;
            float4 va = x4[(size_t)ja * 8 + q];
            float4 vb = x4[(size_t)jb * 8 + q];
            Aa.x = fmaf(wa, va.x, Aa.x); Aa.y = fmaf(wa, va.y, Aa.y);
            Aa.z = fmaf(wa, va.z, Aa.z); Aa.w = fmaf(wa, va.w, Aa.w);
            Ab.x = fmaf(wb, vb.x, Ab.x); Ab.y = fmaf(wb, vb.y, Ab.y);
            Ab.z = fmaf(wb, vb.z, Ab.z); Ab.w = fmaf(wb, vb.w, Ab.w);
        }
    }

    // ---- Words k=2,3 guarded per row (positions 16..31 per shard).
#pragma unroll
    for (int k = 2; k < 4; k++) {
        if (mca > (k << 3)) {
#pragma unroll
            for (int u = 0; u < 8; u++) {
                int slot = (u << 2) + g;
                int j = __shfl_sync(0xffffffffu, ia[k], slot);
                float w = ((k << 3) + u < cga) ? 1.0f : 0.0f;
                float4 v = x4[(size_t)j * 8 + q];
                Aa.x = fmaf(w, v.x, Aa.x); Aa.y = fmaf(w, v.y, Aa.y);
                Aa.z = fmaf(w, v.z, Aa.z); Aa.w = fmaf(w, v.w, Aa.w);
            }
        }
        if (mcb > (k << 3)) {
#pragma unroll
            for (int u = 0; u < 8; u++) {
                int slot = (u << 2) + g;
                int j = __shfl_sync(0xffffffffu, ib[k], slot);
                float w = ((k << 3) + u < cgb) ? 1.0f : 0.0f;
                float4 v = x4[(size_t)j * 8 + q];
                Ab.x = fmaf(w, v.x, Ab.x); Ab.y = fmaf(w, v.y, Ab.y);
                Ab.z = fmaf(w, v.z, Ab.z); Ab.w = fmaf(w, v.w, Ab.w);
            }
        }
    }

    // ---- Rare tail: words k=4..7 (shard count > 32: ~2e-4 per shard).
    for (int k = 4; k < 8; k++) {
        if (mca > (k << 3)) {
            int ik = __ldg(la + (k << 5) + lane);
            for (int u = 0; u < 8; u++) {
                int slot = (u << 2) + g;
                int j = __shfl_sync(0xffffffffu, ik, slot);
                float w = ((k << 3) + u < cga) ? 1.0f : 0.0f;
                float4 v = x4[(size_t)j * 8 + q];
                Aa.x = fmaf(w, v.x, Aa.x); Aa.y = fmaf(w, v.y, Aa.y);
                Aa.z = fmaf(w, v.z, Aa.z); Aa.w = fmaf(w, v.w, Aa.w);
            }
        }
        if (mcb > (k << 3)) {
            int ik = __ldg(lb + (k << 5) + lane);
            for (int u = 0; u < 8; u++) {
                int slot = (u << 2) + g;
                int j = __shfl_sync(0xffffffffu, ik, slot);
                float w = ((k << 3) + u < cgb) ? 1.0f : 0.0f;
                float4 v = x4[(size_t)j * 8 + q];
                Ab.x = fmaf(w, v.x, Ab.x); Ab.y = fmaf(w, v.y, Ab.y);
                Ab.z = fmaf(w, v.z, Ab.z); Ab.w = fmaf(w, v.w, Ab.w);
            }
        }
    }

    // Blanket clear of both rows' 2KB bitmask stripes (coalesced STG.128).
    {
        uint4* ra = reinterpret_cast<uint4*>(g_bits + (size_t)r0 * WPR);
        uint4* rb = reinterpret_cast<uint4*>(g_bits + (size_t)r1 * WPR);
        const uint4 z = make_uint4(0u, 0u, 0u, 0u);
        ra[lane] = z; ra[lane + 32] = z; ra[lane + 64] = z; ra[lane + 96] = z;
        rb[lane] = z; rb[lane + 32] = z; rb[lane + 64] = z; rb[lane + 96] = z;
    }

    // Cross-group reduce for both rows (xor 8, xor 16).
#pragma unroll
    for (int off = 8; off <= 16; off <<= 1) {
        Aa.x += __shfl_xor_sync(0xffffffffu, Aa.x, off);
        Aa.y += __shfl_xor_sync(0xffffffffu, Aa.y, off);
        Aa.z += __shfl_xor_sync(0xffffffffu, Aa.z, off);
        Aa.w += __shfl_xor_sync(0xffffffffu, Aa.w, off);
        Ab.x += __shfl_xor_sync(0xffffffffu, Ab.x, off);
        Ab.y += __shfl_xor_sync(0xffffffffu, Ab.y, off);
        Ab.z += __shfl_xor_sync(0xffffffffu, Ab.z, off);
        Ab.w += __shfl_xor_sync(0xffffffffu, Ab.w, off);
    }
    int w2 = warp * 2;
    if (lane < 8) {
        *reinterpret_cast<float4*>(&msgsm[w2][q << 2])     = Aa;
        *reinterpret_cast<float4*>(&msgsm[w2 + 1][q << 2]) = Ab;
    }
    xsm[w2][lane]     = xa;
    xsm[w2 + 1][lane] = xb;
    __syncwarp();

    // Dual fused epilogue.
    float oa = bsum[lane];
    float ob = oa;
#pragma unroll
    for (int d = 0; d < DD; d++) {
        float wag = WaggT[d * DD + lane];
        float wup = WupdT[d * DD + lane];
        oa = fmaf(msgsm[w2][d],     wag, fmaf(xsm[w2][d],     wup, oa));
        ob = fmaf(msgsm[w2 + 1][d], wag, fmaf(xsm[w2 + 1][d], wup, ob));
    }
    out[(size_t)r0 * DD + lane] = oa;
    out[(size_t)r1 * DD + lane] = ob;
}

extern "C" void kernel_launch(void* const* d_in, const int* in_sizes, int n_in,
                              void* d_out, int out_size) {
    const float* x     = (const float*)d_in[0];
    const int*   ei    = (const int*)d_in[1];     // [2, E]: row0=src, row1=dst
    const float* W_agg = (const float*)d_in[2];
    const float* b_agg = (const float*)d_in[3];
    const float* W_upd = (const float*)d_in[4];
    const float* b_upd = (const float*)d_in[5];
    float* out = (float*)d_out;

    int E  = in_sizes[1] / 2;
    int E2 = E / 2;                               // E = 524288, divisible by 2

    build_kernel<<<(E2 + 255) / 256, 256>>>(ei, ei + E, E2);
    agg_kernel<<<NN / 16, 256>>>(x, W_agg, b_agg, W_upd, b_upd, out);
}

// round 16
// speedup vs baseline: 1.1789x; 1.1197x over previous
#include <cuda_runtime.h>
#include <stdint.h>

#define NN 16384
#define DD 32
#define WPR (NN / 32)     // 512 u32 per dedup-bitmask row
#define LCAP 256          // per-node list capacity

// Canonical-pair dedup bitmask: bit for pair {a,b} (a<=b) lives at
// g_bits[a*WPR + (b>>5)]. agg blanket-clears each row stripe per launch.
__device__ uint32_t g_bits[(size_t)NN * WPR];
__device__ int g_list[(size_t)NN * LCAP];
__device__ int g_cnt[NN];

// 2 edges per thread, 1024 blocks. ONE canonical atomicOr per edge.
__global__ void __launch_bounds__(256) build_kernel(const int* __restrict__ src,
                                                    const int* __restrict__ dst,
                                                    int E2) {
    int t = blockIdx.x * blockDim.x + threadIdx.x;
    if (t >= E2) return;
    int2 s2 = __ldg(reinterpret_cast<const int2*>(src) + t);
    int2 d2 = __ldg(reinterpret_cast<const int2*>(dst) + t);

    int s[2] = {s2.x, s2.y};
    int d[2] = {d2.x, d2.y};

    int a[2], b[2];
#pragma unroll
    for (int i = 0; i < 2; i++) {
        a[i] = s[i] < d[i] ? s[i] : d[i];
        b[i] = s[i] < d[i] ? d[i] : s[i];
    }

    unsigned old[2];
#pragma unroll
    for (int i = 0; i < 2; i++)
        old[i] = atomicOr(&g_bits[(size_t)a[i] * WPR + (b[i] >> 5)], 1u << (b[i] & 31));

#pragma unroll
    for (int i = 0; i < 2; i++) {
        if (!(old[i] & (1u << (b[i] & 31)))) {    // first time pair {a,b} seen
            int p = atomicAdd(&g_cnt[a[i]], 1);
            if (p < LCAP) g_list[(size_t)a[i] * LCAP + p] = b[i];
            if (a[i] != b[i]) {
                int p2 = atomicAdd(&g_cnt[b[i]], 1);
                if (p2 < LCAP) g_list[(size_t)b[i] * LCAP + p2] = a[i];
            }
        }
    }
}

// FOUR rows per warp: 64 independent LDG.128 in one straight-line block
// (saturates the ~55 outstanding-LDG/warp cap). Guarded on-demand extension
// for slots 64..95, rare tail, blanket clears, quad fused epilogue.
__global__ void __launch_bounds__(256, 4) agg_kernel(const float* __restrict__ x,
                                                     const float* __restrict__ W_agg,
                                                     const float* __restrict__ b_agg,
                                                     const float* __restrict__ W_upd,
                                                     const float* __restrict__ b_upd,
                                                     float* __restrict__ out) {
    __shared__ float WaggT[DD * DD];   // [d][c] = W_agg[c][d]
    __shared__ float WupdT[DD * DD];
    __shared__ float bsum[DD];
    __shared__ float msgsm[32][DD];
    __shared__ float xsm[32][DD];

    int tid  = threadIdx.x;
    int warp = tid >> 5;
    int lane = tid & 31;
    int rbase = blockIdx.x * 32 + warp * 4;   // rows rbase..rbase+3

    // Front-batched independent loads: 2 index words + cnt + x row, x4 rows.
    int i0[4], i1[4], cnt[4];
    float xo[4];
#pragma unroll
    for (int m = 0; m < 4; m++) {
        const int* lm = g_list + (size_t)(rbase + m) * LCAP;
        i0[m] = __ldg(lm + lane);
        i1[m] = __ldg(lm + 32 + lane);
        cnt[m] = g_cnt[rbase + m];
        cnt[m] = cnt[m] < LCAP ? cnt[m] : LCAP;
        xo[m] = x[(size_t)(rbase + m) * DD + lane];
    }
    if (lane < 4) g_cnt[rbase + lane] = 0;    // reset for next replay

    for (int i = tid; i < DD * DD; i += blockDim.x) {
        int c = i >> 5, d = i & 31;
        WaggT[d * DD + c] = W_agg[i];
        WupdT[d * DD + c] = W_upd[i];
    }
    if (tid < DD) bsum[tid] = b_agg[tid] + b_upd[tid];
    __syncthreads();

    int g = lane >> 3;        // gather group 0..3
    int q = lane & 7;         // float4 slot within a 128B row

    const float4* x4 = reinterpret_cast<const float4*>(x);
    float4 A[4];
#pragma unroll
    for (int m = 0; m < 4; m++) A[m] = make_float4(0.f, 0.f, 0.f, 0.f);

    // ---- Slots 0..63 of ALL FOUR rows: 64 independent LDG.128, straight-line.
#pragma unroll
    for (int u = 0; u < 8; u++) {
        int slot = (u << 2) + g;
#pragma unroll
        for (int m = 0; m < 4; m++) {
            int j = __shfl_sync(0xffffffffu, i0[m], slot);
            float w = (slot < cnt[m]) ? 1.0f : 0.0f;
            float4 v = x4[(size_t)j * 8 + q];
            A[m].x = fmaf(w, v.x, A[m].x); A[m].y = fmaf(w, v.y, A[m].y);
            A[m].z = fmaf(w, v.z, A[m].z); A[m].w = fmaf(w, v.w, A[m].w);
        }
    }
#pragma unroll
    for (int u = 0; u < 8; u++) {
        int slot = (u << 2) + g;
#pragma unroll
        for (int m = 0; m < 4; m++) {
            int j = __shfl_sync(0xffffffffu, i1[m], slot);
            float w = (32 + slot < cnt[m]) ? 1.0f : 0.0f;
            float4 v = x4[(size_t)j * 8 + q];
            A[m].x = fmaf(w, v.x, A[m].x); A[m].y = fmaf(w, v.y, A[m].y);
            A[m].z = fmaf(w, v.z, A[m].z); A[m].w = fmaf(w, v.w, A[m].w);
        }
    }

    // ---- Slots 64..95 per row (on-demand index load; ~47% of rows).
#pragma unroll
    for (int m = 0; m < 4; m++) {
        if (cnt[m] > 64) {
            int i2 = __ldg(g_list + (size_t)(rbase + m) * LCAP + 64 + lane);
            int ng = cnt[m] - 64;  ng = ng > 32 ? 32 : ng;
            int nu = (ng + 3) >> 2;
#pragma unroll
            for (int u = 0; u < 8; u++) {
                if (u < nu) {
                    int slot = (u << 2) + g;
                    int j = __shfl_sync(0xffffffffu, i2, slot);
                    float w = (slot < ng) ? 1.0f : 0.0f;
                    float4 v = x4[(size_t)j * 8 + q];
                    A[m].x = fmaf(w, v.x, A[m].x); A[m].y = fmaf(w, v.y, A[m].y);
                    A[m].z = fmaf(w, v.z, A[m].z); A[m].w = fmaf(w, v.w, A[m].w);
                }
            }
        }
    }

    // ---- Rare tail: slots 96..255 (Poisson(64): ~never; correctness only).
#pragma unroll 1
    for (int m = 0; m < 4; m++) {
        for (int k = 3; k < 8; k++) {
            int base = k << 5;
            if (base >= cnt[m]) break;
            int ik = __ldg(g_list + (size_t)(rbase + m) * LCAP + base + lane);
            int ng = cnt[m] - base;  ng = ng > 32 ? 32 : ng;
            int nu = (ng + 3) >> 2;
            for (int u = 0; u < 8; u++) {
                if (u < nu) {
                    int slot = (u << 2) + g;
                    int j = __shfl_sync(0xffffffffu, ik, slot);
                    float w = (slot < ng) ? 1.0f : 0.0f;
                    float4 v = x4[(size_t)j * 8 + q];
                    A[m].x = fmaf(w, v.x, A[m].x); A[m].y = fmaf(w, v.y, A[m].y);
                    A[m].z = fmaf(w, v.z, A[m].z); A[m].w = fmaf(w, v.w, A[m].w);
                }
            }
        }
    }

    // Blanket clear of all four rows' 2KB bitmask stripes (coalesced STG.128).
    {
        const uint4 z = make_uint4(0u, 0u, 0u, 0u);
#pragma unroll
        for (int m = 0; m < 4; m++) {
            uint4* rv = reinterpret_cast<uint4*>(g_bits + (size_t)(rbase + m) * WPR);
            rv[lane] = z; rv[lane + 32] = z; rv[lane + 64] = z; rv[lane + 96] = z;
        }
    }

    // Cross-group reduce for all rows (xor 8, xor 16).
#pragma unroll
    for (int off = 8; off <= 16; off <<= 1) {
#pragma unroll
        for (int m = 0; m < 4; m++) {
            A[m].x += __shfl_xor_sync(0xffffffffu, A[m].x, off);
            A[m].y += __shfl_xor_sync(0xffffffffu, A[m].y, off);
            A[m].z += __shfl_xor_sync(0xffffffffu, A[m].z, off);
            A[m].w += __shfl_xor_sync(0xffffffffu, A[m].w, off);
        }
    }
    int w4 = warp * 4;
    if (lane < 8) {
#pragma unroll
        for (int m = 0; m < 4; m++)
            *reinterpret_cast<float4*>(&msgsm[w4 + m][q << 2]) = A[m];
    }
#pragma unroll
    for (int m = 0; m < 4; m++) xsm[w4 + m][lane] = xo[m];
    __syncwarp();

    // Quad fused epilogue.
    float o0 = bsum[lane], o1 = o0, o2 = o0, o3 = o0;
#pragma unroll
    for (int d = 0; d < DD; d++) {
        float wag = WaggT[d * DD + lane];
        float wup = WupdT[d * DD + lane];
        o0 = fmaf(msgsm[w4 + 0][d], wag, fmaf(xsm[w4 + 0][d], wup, o0));
        o1 = fmaf(msgsm[w4 + 1][d], wag, fmaf(xsm[w4 + 1][d], wup, o1));
        o2 = fmaf(msgsm[w4 + 2][d], wag, fmaf(xsm[w4 + 2][d], wup, o2));
        o3 = fmaf(msgsm[w4 + 3][d], wag, fmaf(xsm[w4 + 3][d], wup, o3));
    }
    out[(size_t)(rbase + 0) * DD + lane] = o0;
    out[(size_t)(rbase + 1) * DD + lane] = o1;
    out[(size_t)(rbase + 2) * DD + lane] = o2;
    out[(size_t)(rbase + 3) * DD + lane] = o3;
}

extern "C" void kernel_launch(void* const* d_in, const int* in_sizes, int n_in,
                              void* d_out, int out_size) {
    const float* x     = (const float*)d_in[0];
    const int*   ei    = (const int*)d_in[1];     // [2, E]: row0=src, row1=dst
    const float* W_agg = (const float*)d_in[2];
    const float* b_agg = (const float*)d_in[3];
    const float* W_upd = (const float*)d_in[4];
    const float* b_upd = (const float*)d_in[5];
    float* out = (float*)d_out;

    int E  = in_sizes[1] / 2;
    int E2 = E / 2;                               // E = 524288, divisible by 2

    build_kernel<<<(E2 + 255) / 256, 256>>>(ei, ei + E, E2);
    agg_kernel<<<NN / 32, 256>>>(x, W_agg, b_agg, W_upd, b_upd, out);
}

// round 17
// speedup vs baseline: 1.4149x; 1.2002x over previous
#include <cuda_runtime.h>
#include <stdint.h>

#define NN 16384
#define DD 32
#define WPR (NN / 32)     // 512 u32 per bitmask row (2KB)
#define LCAPS 192         // smem neighbor-list capacity per row (deg max ~110)

// FULL symmetric adjacency bitmask (32 MB): bit j of row r <=> edge {r,j}.
// Zero at module load; agg reads+clears each row stripe every launch.
// No lists, no counters -- build is pure fire-and-forget REDG.OR.
__device__ uint32_t g_bits[(size_t)NN * WPR];

__device__ __forceinline__ void red_or(uint32_t* addr, uint32_t val) {
    asm volatile("red.global.or.b32 [%0], %1;" :: "l"(addr), "r"(val) : "memory");
}

// 2 edges per thread: 2 int2 loads + 4 non-returning REDG.OR. No chains.
__global__ void __launch_bounds__(256) build_kernel(const int* __restrict__ src,
                                                    const int* __restrict__ dst,
                                                    int E2) {
    int t = blockIdx.x * blockDim.x + threadIdx.x;
    if (t >= E2) return;
    int2 s2 = __ldg(reinterpret_cast<const int2*>(src) + t);
    int2 d2 = __ldg(reinterpret_cast<const int2*>(dst) + t);

    red_or(&g_bits[(size_t)s2.x * WPR + (d2.x >> 5)], 1u << (d2.x & 31));
    red_or(&g_bits[(size_t)d2.x * WPR + (s2.x >> 5)], 1u << (s2.x & 31));
    red_or(&g_bits[(size_t)s2.y * WPR + (d2.y >> 5)], 1u << (d2.y & 31));
    red_or(&g_bits[(size_t)d2.y * WPR + (s2.y >> 5)], 1u << (s2.y & 31));
}

// FOUR rows per warp. Per row: load 2KB bitmask stripe, lane-parallel extract
// set bits into smem list (popc + warp scan + short ffs loop), clear stripe,
// then the R16 quad gather (64 straight-line LDG.128) from the smem lists.
__global__ void __launch_bounds__(256, 4) agg_kernel(const float* __restrict__ x,
                                                     const float* __restrict__ W_agg,
                                                     const float* __restrict__ b_agg,
                                                     const float* __restrict__ W_upd,
                                                     const float* __restrict__ b_upd,
                                                     float* __restrict__ out) {
    __shared__ float WaggT[DD * DD];   // [d][c] = W_agg[c][d]
    __shared__ float WupdT[DD * DD];
    __shared__ float bsum[DD];
    __shared__ float msgsm[32][DD];
    __shared__ float xsm[32][DD];
    __shared__ int   lst[32][LCAPS];   // 24KB: per-row neighbor lists

    int tid  = threadIdx.x;
    int warp = tid >> 5;
    int lane = tid & 31;
    int rbase = blockIdx.x * 32 + warp * 4;   // rows rbase..rbase+3
    int w4 = warp * 4;

    float xo[4];
#pragma unroll
    for (int m = 0; m < 4; m++)
        xo[m] = x[(size_t)(rbase + m) * DD + lane];

    for (int i = tid; i < DD * DD; i += blockDim.x) {
        int c = i >> 5, d = i & 31;
        WaggT[d * DD + c] = W_agg[i];
        WupdT[d * DD + c] = W_upd[i];
    }
    if (tid < DD) bsum[tid] = b_agg[tid] + b_upd[tid];

    // ---- Extraction: per row, read 4 uint4/lane, popc+scan+emit, clear.
    int cnt[4];
#pragma unroll
    for (int m = 0; m < 4; m++) {
        uint4* bv = reinterpret_cast<uint4*>(g_bits + (size_t)(rbase + m) * WPR);
        uint4 a0 = bv[lane];
        uint4 a1 = bv[lane + 32];
        uint4 a2 = bv[lane + 64];
        uint4 a3 = bv[lane + 96];

        int c0 = __popc(a0.x) + __popc(a0.y) + __popc(a0.z) + __popc(a0.w);
        int c1 = __popc(a1.x) + __popc(a1.y) + __popc(a1.z) + __popc(a1.w);
        int c2 = __popc(a2.x) + __popc(a2.y) + __popc(a2.z) + __popc(a2.w);
        int c3 = __popc(a3.x) + __popc(a3.y) + __popc(a3.z) + __popc(a3.w);
        int mycnt = c0 + c1 + c2 + c3;

        // Inclusive warp scan -> exclusive offset + total.
        int inc = mycnt;
#pragma unroll
        for (int dd = 1; dd < 32; dd <<= 1) {
            int n = __shfl_up_sync(0xffffffffu, inc, dd);
            if (lane >= dd) inc += n;
        }
        int total = __shfl_sync(0xffffffffu, inc, 31);
        int off = inc - mycnt;

        // Emit node ids. uint4 chunk c=lane+32k covers nodes [128c, 128c+128).
        int* L = lst[w4 + m];
        uint32_t ws[16] = {a0.x, a0.y, a0.z, a0.w,  a1.x, a1.y, a1.z, a1.w,
                           a2.x, a2.y, a2.z, a2.w,  a3.x, a3.y, a3.z, a3.w};
#pragma unroll
        for (int k = 0; k < 4; k++) {
#pragma unroll
            for (int t2 = 0; t2 < 4; t2++) {
                uint32_t w = ws[k * 4 + t2];
                int base = ((lane + (k << 5)) << 7) + (t2 << 5);
                while (w) {
                    int b = __ffs(w) - 1;
                    w &= w - 1;
                    if (off < LCAPS) L[off] = base + b;
                    off++;
                }
            }
        }

        // Clear stripe for next replay.
        const uint4 z = make_uint4(0u, 0u, 0u, 0u);
        bv[lane] = z; bv[lane + 32] = z; bv[lane + 64] = z; bv[lane + 96] = z;

        cnt[m] = total < LCAPS ? total : LCAPS;
    }
    __syncthreads();   // weights ready + lists visible within warp

    int g = lane >> 3;        // gather group 0..3
    int q = lane & 7;         // float4 slot within a 128B row

    const float4* x4 = reinterpret_cast<const float4*>(x);
    float4 A[4];
#pragma unroll
    for (int m = 0; m < 4; m++) A[m] = make_float4(0.f, 0.f, 0.f, 0.f);

    // ---- Slots 0..63 of ALL FOUR rows: 64 independent LDG.128, straight-line.
    // Stale list slots (>= cnt) are masked to a valid index and zero weight.
#pragma unroll
    for (int u = 0; u < 16; u++) {
        int slot = (u << 2) + g;
#pragma unroll
        for (int m = 0; m < 4; m++) {
            int j = lst[w4 + m][slot] & (NN - 1);
            float w = (slot < cnt[m]) ? 1.0f : 0.0f;
            float4 v = x4[(size_t)j * 8 + q];
            A[m].x = fmaf(w, v.x, A[m].x); A[m].y = fmaf(w, v.y, A[m].y);
            A[m].z = fmaf(w, v.z, A[m].z); A[m].w = fmaf(w, v.w, A[m].w);
        }
    }

    // ---- Slots 64..95 per row (~47% of rows), 96..127 (rare), 128.. (never).
#pragma unroll
    for (int m = 0; m < 4; m++) {
        if (cnt[m] > 64) {
#pragma unroll
            for (int u = 0; u < 8; u++) {
                int slot = 64 + (u << 2) + g;
                int j = lst[w4 + m][slot] & (NN - 1);
                float w = (slot < cnt[m]) ? 1.0f : 0.0f;
                float4 v = x4[(size_t)j * 8 + q];
                A[m].x = fmaf(w, v.x, A[m].x); A[m].y = fmaf(w, v.y, A[m].y);
                A[m].z = fmaf(w, v.z, A[m].z); A[m].w = fmaf(w, v.w, A[m].w);
            }
        }
        if (cnt[m] > 96) {
            for (int u = 0; u < 8; u++) {
                int slot = 96 + (u << 2) + g;
                if (slot < 128) {
                    int j = lst[w4 + m][slot] & (NN - 1);
                    float w = (slot < cnt[m]) ? 1.0f : 0.0f;
                    float4 v = x4[(size_t)j * 8 + q];
                    A[m].x = fmaf(w, v.x, A[m].x); A[m].y = fmaf(w, v.y, A[m].y);
                    A[m].z = fmaf(w, v.z, A[m].z); A[m].w = fmaf(w, v.w, A[m].w);
                }
            }
        }
        if (cnt[m] > 128) {
            for (int slot = 128 + g; slot < cnt[m]; slot += 4) {
                int j = lst[w4 + m][slot] & (NN - 1);
                float4 v = x4[(size_t)j * 8 + q];
                A[m].x += v.x; A[m].y += v.y; A[m].z += v.z; A[m].w += v.w;
            }
        }
    }

    // Cross-group reduce for all rows (xor 8, xor 16).
#pragma unroll
    for (int off = 8; off <= 16; off <<= 1) {
#pragma unroll
        for (int m = 0; m < 4; m++) {
            A[m].x += __shfl_xor_sync(0xffffffffu, A[m].x, off);
            A[m].y += __shfl_xor_sync(0xffffffffu, A[m].y, off);
            A[m].z += __shfl_xor_sync(0xffffffffu, A[m].z, off);
            A[m].w += __shfl_xor_sync(0xffffffffu, A[m].w, off);
        }
    }
    if (lane < 8) {
#pragma unroll
        for (int m = 0; m < 4; m++)
            *reinterpret_cast<float4*>(&msgsm[w4 + m][q << 2]) = A[m];
    }
#pragma unroll
    for (int m = 0; m < 4; m++) xsm[w4 + m][lane] = xo[m];
    __syncwarp();

    // Quad fused epilogue.
    float o0 = bsum[lane], o1 = o0, o2 = o0, o3 = o0;
#pragma unroll
    for (int d = 0; d < DD; d++) {
        float wag = WaggT[d * DD + lane];
        float wup = WupdT[d * DD + lane];
        o0 = fmaf(msgsm[w4 + 0][d], wag, fmaf(xsm[w4 + 0][d], wup, o0));
        o1 = fmaf(msgsm[w4 + 1][d], wag, fmaf(xsm[w4 + 1][d], wup, o1));
        o2 = fmaf(msgsm[w4 + 2][d], wag, fmaf(xsm[w4 + 2][d], wup, o2));
        o3 = fmaf(msgsm[w4 + 3][d], wag, fmaf(xsm[w4 + 3][d], wup, o3));
    }
    out[(size_t)(rbase + 0) * DD + lane] = o0;
    out[(size_t)(rbase + 1) * DD + lane] = o1;
    out[(size_t)(rbase + 2) * DD + lane] = o2;
    out[(size_t)(rbase + 3) * DD + lane] = o3;
}

extern "C" void kernel_launch(void* const* d_in, const int* in_sizes, int n_in,
                              void* d_out, int out_size) {
    const float* x     = (const float*)d_in[0];
    const int*   ei    = (const int*)d_in[1];     // [2, E]: row0=src, row1=dst
    const float* W_agg = (const float*)d_in[2];
    const float* b_agg = (const float*)d_in[3];
    const float* W_upd = (const float*)d_in[4];
    const float* b_upd = (const float*)d_in[5];
    float* out = (float*)d_out;

    int E  = in_sizes[1] / 2;
    int E2 = E / 2;                               // E = 524288, divisible by 2

    build_kernel<<<(E2 + 255) / 256, 256>>>(ei, ei + E, E2);
    agg_kernel<<<NN / 32, 256>>>(x, W_agg, b_agg, W_upd, b_upd, out);
}